// round 15
// baseline (speedup 1.0000x reference)
#include <cuda_runtime.h>
#include <cuda_fp16.h>
#include <math.h>
#include <stdint.h>

#define NN 384
#define CC 128
#define HH 4
#define MM (NN*NN)

// Scratch (allocation-free: __device__ globals)
__device__ __half d_y[(size_t)MM*512];     // [q|k|v|g] as fp16, q pre-scaled
__device__ __half d_bias[(size_t)HH*MM];   // bias[h, q, k] (fp16; computed fp32)
__device__ __half d_o[(size_t)MM*CC];      // attention output (fp16)

// ---- fp16 tensor-core helpers (m16n8k16, fp32 accum) ----
__device__ __forceinline__ void mma_f16(float& c0, float& c1, float& c2, float& c3,
                                        unsigned a0, unsigned a1, unsigned a2, unsigned a3,
                                        unsigned b0, unsigned b1) {
    asm("mma.sync.aligned.m16n8k16.row.col.f32.f16.f16.f32 "
        "{%0,%1,%2,%3}, {%4,%5,%6,%7}, {%8,%9}, {%0,%1,%2,%3};"
        : "+f"(c0), "+f"(c1), "+f"(c2), "+f"(c3)
        : "r"(a0), "r"(a1), "r"(a2), "r"(a3), "r"(b0), "r"(b1));
}
__device__ __forceinline__ unsigned h2u(float lo, float hi) {
    __half2 h = __floats2half2_rn(lo, hi);
    return reinterpret_cast<unsigned&>(h);
}

// ---------------------------------------------------------------------------
// Kernel 1: projections with FUSED LayerNorm (+ pair-bias on ph==0 blocks).
// Grid (148,2). Block keeps 256 W cols resident; X tiles staged from `pair`
// with LN applied in-warp during staging (row = j*8+warp, lane = col/4).
// Double-buffered prefetch. Warp = m32 x 64 cols, fp16 m16n8k16.
// ---------------------------------------------------------------------------
#define PJW 136
#define PROJ_SMEM_BYTES ((256*PJW + 2*64*PJW) * 2)   // 104448

__global__ __launch_bounds__(256, 2) void proj_fused(
    const float* __restrict__ pair,
    const float* __restrict__ ln_w, const float* __restrict__ ln_b,
    const float* __restrict__ w_bias,
    const float* __restrict__ wq, const float* __restrict__ wk,
    const float* __restrict__ wv, const float* __restrict__ wg)
{
    extern __shared__ char psm[];
    __half* Wt = (__half*)psm;                 // [256][136]
    __half* Xb = Wt + 256 * PJW;               // [2][64][136]

    int tid = threadIdx.x, lane = tid & 31, warp = tid >> 5;
    int g = lane >> 2, t = lane & 3;
    int slot = blockIdx.x;
    int ph = blockIdx.y;                       // 0: wq|wk (+bias), 1: wv|wg
    int mhalf = warp >> 2;
    int cq = warp & 3;

    // Lane-resident LN / bias params (lane owns cols lane*4..+3)
    float4 lw = ((const float4*)ln_w)[lane];
    float4 lb = ((const float4*)ln_b)[lane];
    float4 wb0 = ((const float4*)w_bias)[lane * 4 + 0];
    float4 wb1 = ((const float4*)w_bias)[lane * 4 + 1];
    float4 wb2 = ((const float4*)w_bias)[lane * 4 + 2];
    float4 wb3 = ((const float4*)w_bias)[lane * 4 + 3];

    // LN + (optional bias) + fp16 store to smem. Full-warp collective.
    auto ln_stage = [&](float4 v, int grow, __half* dst) {
        float s  = v.x + v.y + v.z + v.w;
        float sq = v.x*v.x + v.y*v.y + v.z*v.z + v.w*v.w;
        #pragma unroll
        for (int o = 16; o; o >>= 1) {
            s  += __shfl_xor_sync(0xffffffffu, s,  o);
            sq += __shfl_xor_sync(0xffffffffu, sq, o);
        }
        float mean = s * (1.0f / CC);
        float var  = sq * (1.0f / CC) - mean * mean;
        float inv  = rsqrtf(var + 1e-5f);
        float x0 = (v.x - mean) * inv * lw.x + lb.x;
        float x1 = (v.y - mean) * inv * lw.y + lb.y;
        float x2 = (v.z - mean) * inv * lw.z + lb.z;
        float x3 = (v.w - mean) * inv * lw.w + lb.w;
        uint2 o2;
        o2.x = h2u(x0, x1);
        o2.y = h2u(x2, x3);
        *(uint2*)dst = o2;
        if (ph == 0) {
            float b0 = x0*wb0.x + x1*wb1.x + x2*wb2.x + x3*wb3.x;
            float b1 = x0*wb0.y + x1*wb1.y + x2*wb2.y + x3*wb3.y;
            float b2 = x0*wb0.z + x1*wb1.z + x2*wb2.z + x3*wb3.z;
            float b3 = x0*wb0.w + x1*wb1.w + x2*wb2.w + x3*wb3.w;
            #pragma unroll
            for (int o = 16; o; o >>= 1) {
                b0 += __shfl_xor_sync(0xffffffffu, b0, o);
                b1 += __shfl_xor_sync(0xffffffffu, b1, o);
                b2 += __shfl_xor_sync(0xffffffffu, b2, o);
                b3 += __shfl_xor_sync(0xffffffffu, b3, o);
            }
            if (lane == 0) {
                d_bias[(size_t)0 * MM + grow] = __float2half(b0);
                d_bias[(size_t)1 * MM + grow] = __float2half(b1);
                d_bias[(size_t)2 * MM + grow] = __float2half(b2);
                d_bias[(size_t)3 * MM + grow] = __float2half(b3);
            }
        }
    };

    // Stage resident W
    const float* w0 = (ph == 0) ? wq : wv;
    const float* w1 = (ph == 0) ? wk : wg;
    for (int i = tid; i < 256 * 128; i += 256) {
        int n = i & 255, k = i >> 8;
        const float* w = (n < 128) ? w0 : w1;
        Wt[n * PJW + k] = __float2half(w[(size_t)k * 128 + (n & 127)]);
    }

    // Stage first X tile (with LN)
    {
        int m0 = slot * 64;
        #pragma unroll
        for (int j = 0; j < 8; j++) {
            int row = j * 8 + warp;
            float4 v = *(const float4*)&pair[(size_t)(m0 + row) * 128 + lane * 4];
            ln_stage(v, m0 + row, &Xb[row * PJW + lane * 4]);
        }
    }
    __syncthreads();

    float scale = (ph == 0 && cq < 2) ? 0.17677669529663687f : 1.0f;
    int colbase = cq * 64;
    int buf = 0;

    for (int mtile = slot; mtile < 2304; mtile += 148) {
        int mnext = mtile + 148;
        bool has_next = (mnext < 2304);

        float4 pf[8];
        if (has_next) {
            const float* src = pair + (size_t)(mnext * 64) * 128;
            #pragma unroll
            for (int j = 0; j < 8; j++)
                pf[j] = *(const float4*)&src[(size_t)(j * 8 + warp) * 128 + lane * 4];
        }

        const __half* Xs = Xb + buf * (64 * PJW);
        float c[16][4];
        #pragma unroll
        for (int i = 0; i < 16; i++)
            #pragma unroll
            for (int j = 0; j < 4; j++) c[i][j] = 0.f;

        int r0 = mhalf * 32;
        #pragma unroll
        for (int k16 = 0; k16 < 8; k16++) {
            int k0 = k16 * 16;
            unsigned a0 = *(const unsigned*)&Xs[(r0 + g) * PJW + k0 + 2*t];
            unsigned a1 = *(const unsigned*)&Xs[(r0 + 8 + g) * PJW + k0 + 2*t];
            unsigned a2 = *(const unsigned*)&Xs[(r0 + g) * PJW + k0 + 2*t + 8];
            unsigned a3 = *(const unsigned*)&Xs[(r0 + 8 + g) * PJW + k0 + 2*t + 8];
            unsigned a4 = *(const unsigned*)&Xs[(r0 + 16 + g) * PJW + k0 + 2*t];
            unsigned a5 = *(const unsigned*)&Xs[(r0 + 24 + g) * PJW + k0 + 2*t];
            unsigned a6 = *(const unsigned*)&Xs[(r0 + 16 + g) * PJW + k0 + 2*t + 8];
            unsigned a7 = *(const unsigned*)&Xs[(r0 + 24 + g) * PJW + k0 + 2*t + 8];
            #pragma unroll
            for (int nb = 0; nb < 8; nb++) {
                int n = colbase + nb * 8 + g;
                unsigned b0 = *(const unsigned*)&Wt[n * PJW + k0 + 2*t];
                unsigned b1 = *(const unsigned*)&Wt[n * PJW + k0 + 2*t + 8];
                mma_f16(c[nb][0], c[nb][1], c[nb][2], c[nb][3],
                        a0, a1, a2, a3, b0, b1);
                mma_f16(c[8+nb][0], c[8+nb][1], c[8+nb][2], c[8+nb][3],
                        a4, a5, a6, a7, b0, b1);
            }
        }

        {
            int r = mtile * 64 + mhalf * 32;
            #pragma unroll
            for (int nb = 0; nb < 8; nb++) {
                int col = ph * 256 + colbase + nb * 8 + 2 * t;
                *(unsigned*)&d_y[(size_t)(r + g) * 512 + col] =
                    h2u(c[nb][0] * scale, c[nb][1] * scale);
                *(unsigned*)&d_y[(size_t)(r + 8 + g) * 512 + col] =
                    h2u(c[nb][2] * scale, c[nb][3] * scale);
                *(unsigned*)&d_y[(size_t)(r + 16 + g) * 512 + col] =
                    h2u(c[8+nb][0] * scale, c[8+nb][1] * scale);
                *(unsigned*)&d_y[(size_t)(r + 24 + g) * 512 + col] =
                    h2u(c[8+nb][2] * scale, c[8+nb][3] * scale);
            }
        }

        __syncthreads();
        if (has_next) {
            __half* dst = Xb + (buf ^ 1) * (64 * PJW);
            int mb = mnext * 64;
            #pragma unroll
            for (int j = 0; j < 8; j++) {
                int row = j * 8 + warp;
                ln_stage(pf[j], mb + row, &dst[row * PJW + lane * 4]);
            }
        }
        __syncthreads();
        buf ^= 1;
    }
}

// ---------------------------------------------------------------------------
// Kernel 2: attention per (b,h), fp16 m16n8k16 flash. Bias read as fp16.
// ---------------------------------------------------------------------------
#define AKS 40
#define AVS 392
#define ATTN_SMEM_BYTES (384*AKS*2 + 32*AVS*2 + 384*4)

__global__ __launch_bounds__(256) void attn_fp16(const int* __restrict__ mask)
{
    extern __shared__ char asm_[];
    __half* Ks = (__half*)asm_;                     // [384][40]
    __half* Vt = Ks + 384 * AKS;                    // [32][392]
    float*  Am = (float*)(Vt + 32 * AVS);           // [384]

    int b = blockIdx.x, h = blockIdx.y;
    int tid = threadIdx.x, lane = tid & 31, w = tid >> 5;
    int g = lane >> 2, t = lane & 3;
    const __half* Yb = d_y + (size_t)b * (NN * 512);

    for (int idx = tid; idx < 384 * 8; idx += 256) {
        int key = idx >> 3, d4 = (idx & 7) * 4;
        uint2 v = *(const uint2*)&Yb[(size_t)key * 512 + 128 + h * 32 + d4];
        *(uint2*)&Ks[key * AKS + d4] = v;
    }
    for (int idx = tid; idx < 384 * 32; idx += 256) {
        int key = idx >> 5, d = idx & 31;
        Vt[d * AVS + key] = Yb[(size_t)key * 512 + 256 + h * 32 + d];
    }
    for (int k = tid; k < NN; k += 256)
        Am[k] = (mask[(size_t)b * NN + k] != 0) ? 0.f : -1e9f;
    __syncthreads();

    for (int mt = w; mt < 24; mt += 8) {
        int q0 = mt * 16;

        unsigned aq[2][4];
        #pragma unroll
        for (int s = 0; s < 2; s++) {
            int dc = h * 32 + 16 * s + 2 * t;
            aq[s][0] = *(const unsigned*)&Yb[(size_t)(q0 + g) * 512 + dc];
            aq[s][1] = *(const unsigned*)&Yb[(size_t)(q0 + 8 + g) * 512 + dc];
            aq[s][2] = *(const unsigned*)&Yb[(size_t)(q0 + g) * 512 + dc + 8];
            aq[s][3] = *(const unsigned*)&Yb[(size_t)(q0 + 8 + g) * 512 + dc + 8];
        }

        float oc[4][4];
        #pragma unroll
        for (int dn = 0; dn < 4; dn++)
            #pragma unroll
            for (int j = 0; j < 4; j++) oc[dn][j] = 0.f;
        float sum_lo = 0.f, sum_hi = 0.f;

        const __half* br_lo = d_bias + (size_t)h * MM + (size_t)(q0 + g) * NN;
        const __half* br_hi = br_lo + (size_t)8 * NN;

        for (int kb = 0; kb < 6; kb++) {
            float pc[8][4];

            #pragma unroll
            for (int nb = 0; nb < 8; nb++) {
                int k8 = kb * 64 + nb * 8;
                float c0 = 0.f, c1 = 0.f, c2 = 0.f, c3 = 0.f;
                #pragma unroll
                for (int s = 0; s < 2; s++) {
                    unsigned b0 = *(const unsigned*)&Ks[(k8 + g) * AKS + 16*s + 2*t];
                    unsigned b1 = *(const unsigned*)&Ks[(k8 + g) * AKS + 16*s + 2*t + 8];
                    mma_f16(c0, c1, c2, c3,
                            aq[s][0], aq[s][1], aq[s][2], aq[s][3], b0, b1);
                }
                int col = k8 + 2 * t;
                float2 blo = __half22float2(*(const __half2*)&br_lo[col]);
                float2 bhi = __half22float2(*(const __half2*)&br_hi[col]);
                float2 am  = *(const float2*)&Am[col];
                float e0 = __expf(c0 + blo.x + am.x);
                float e1 = __expf(c1 + blo.y + am.y);
                float e2 = __expf(c2 + bhi.x + am.x);
                float e3 = __expf(c3 + bhi.y + am.y);
                sum_lo += e0 + e1;
                sum_hi += e2 + e3;
                pc[nb][0] = e0; pc[nb][1] = e1; pc[nb][2] = e2; pc[nb][3] = e3;
            }

            #pragma unroll
            for (int j = 0; j < 4; j++) {
                unsigned a0 = h2u(pc[2*j][0],   pc[2*j][1]);
                unsigned a1 = h2u(pc[2*j][2],   pc[2*j][3]);
                unsigned a2 = h2u(pc[2*j+1][0], pc[2*j+1][1]);
                unsigned a3 = h2u(pc[2*j+1][2], pc[2*j+1][3]);
                int kg = kb * 64 + j * 16;
                #pragma unroll
                for (int dn = 0; dn < 4; dn++) {
                    unsigned b0 = *(const unsigned*)&Vt[(dn*8 + g) * AVS + kg + 2*t];
                    unsigned b1 = *(const unsigned*)&Vt[(dn*8 + g) * AVS + kg + 2*t + 8];
                    mma_f16(oc[dn][0], oc[dn][1], oc[dn][2], oc[dn][3],
                            a0, a1, a2, a3, b0, b1);
                }
            }
        }

        #pragma unroll
        for (int o = 1; o <= 2; o <<= 1) {
            sum_lo += __shfl_xor_sync(0xffffffffu, sum_lo, o);
            sum_hi += __shfl_xor_sync(0xffffffffu, sum_hi, o);
        }
        float inv_lo = 1.f / sum_lo;
        float inv_hi = 1.f / sum_hi;

        __half* ob = d_o + ((size_t)b * NN + q0) * CC + h * 32;
        #pragma unroll
        for (int dn = 0; dn < 4; dn++) {
            *(unsigned*)&ob[(size_t)g * CC + dn * 8 + 2 * t] =
                h2u(oc[dn][0] * inv_lo, oc[dn][1] * inv_lo);
            *(unsigned*)&ob[(size_t)(g + 8) * CC + dn * 8 + 2 * t] =
                h2u(oc[dn][2] * inv_hi, oc[dn][3] * inv_hi);
        }
    }
}

// ---------------------------------------------------------------------------
// Kernel 3: out = (o * sigmoid(g)) @ wo, persistent-W fp16 m16n8k16.
// ---------------------------------------------------------------------------
#define OGW 136
#define OUT_SMEM_BYTES ((128*OGW + 64*OGW) * 2)

__global__ __launch_bounds__(256) void out_fp16(
    const float* __restrict__ wo, float* __restrict__ out)
{
    extern __shared__ char osm[];
    __half* Wh = (__half*)osm;            // [128][136]
    __half* Ah = Wh + 128 * OGW;          // [64][136]

    int tid = threadIdx.x, lane = tid & 31, warp = tid >> 5;
    int g = lane >> 2, t = lane & 3;
    int mhalf = warp >> 2;
    int cq = warp & 3;

    for (int i = tid; i < 128 * 128; i += 256) {
        int n = i & 127, k = i >> 7;
        Wh[n * OGW + k] = __float2half(wo[(size_t)k * 128 + n]);
    }

    for (int tile = blockIdx.x; tile < 2304; tile += 592) {
        int m0 = tile * 64;
        __syncthreads();
        for (int i = tid; i < 64 * 32; i += 256) {
            int row = i >> 5, c4 = (i & 31) * 4;
            uint2 ou = *(const uint2*)&d_o[(size_t)(m0 + row) * 128 + c4];
            uint2 gu = *(const uint2*)&d_y[(size_t)(m0 + row) * 512 + 384 + c4];
            float2 of01 = __half22float2(reinterpret_cast<__half2&>(ou.x));
            float2 of23 = __half22float2(reinterpret_cast<__half2&>(ou.y));
            float2 gf01 = __half22float2(reinterpret_cast<__half2&>(gu.x));
            float2 gf23 = __half22float2(reinterpret_cast<__half2&>(gu.y));
            float a0 = of01.x * (1.f / (1.f + __expf(-gf01.x)));
            float a1 = of01.y * (1.f / (1.f + __expf(-gf01.y)));
            float a2 = of23.x * (1.f / (1.f + __expf(-gf23.x)));
            float a3 = of23.y * (1.f / (1.f + __expf(-gf23.y)));
            uint2 o;
            o.x = h2u(a0, a1);
            o.y = h2u(a2, a3);
            *(uint2*)&Ah[row * OGW + c4] = o;
        }
        __syncthreads();

        float c[2][4][4];
        #pragma unroll
        for (int mm = 0; mm < 2; mm++)
            #pragma unroll
            for (int nb = 0; nb < 4; nb++)
                #pragma unroll
                for (int j = 0; j < 4; j++) c[mm][nb][j] = 0.f;

        #pragma unroll
        for (int k16 = 0; k16 < 8; k16++) {
            int k0 = k16 * 16;
            #pragma unroll
            for (int mm = 0; mm < 2; mm++) {
                int r0 = mhalf * 32 + mm * 16;
                unsigned a0 = *(const unsigned*)&Ah[(r0 + g) * OGW + k0 + 2*t];
                unsigned a1 = *(const unsigned*)&Ah[(r0 + 8 + g) * OGW + k0 + 2*t];
                unsigned a2 = *(const unsigned*)&Ah[(r0 + g) * OGW + k0 + 2*t + 8];
                unsigned a3 = *(const unsigned*)&Ah[(r0 + 8 + g) * OGW + k0 + 2*t + 8];
                #pragma unroll
                for (int nb = 0; nb < 4; nb++) {
                    int n = cq * 32 + nb * 8 + g;
                    unsigned b0 = *(const unsigned*)&Wh[n * OGW + k0 + 2*t];
                    unsigned b1 = *(const unsigned*)&Wh[n * OGW + k0 + 2*t + 8];
                    mma_f16(c[mm][nb][0], c[mm][nb][1], c[mm][nb][2], c[mm][nb][3],
                            a0, a1, a2, a3, b0, b1);
                }
            }
        }

        #pragma unroll
        for (int mm = 0; mm < 2; mm++) {
            int r = m0 + mhalf * 32 + mm * 16;
            #pragma unroll
            for (int nb = 0; nb < 4; nb++) {
                int col = cq * 32 + nb * 8 + 2 * t;
                *(float2*)&out[(size_t)(r + g) * 128 + col] =
                    make_float2(c[mm][nb][0], c[mm][nb][1]);
                *(float2*)&out[(size_t)(r + 8 + g) * 128 + col] =
                    make_float2(c[mm][nb][2], c[mm][nb][3]);
            }
        }
    }
}

// ---------------------------------------------------------------------------
extern "C" void kernel_launch(void* const* d_in, const int* in_sizes, int n_in,
                              void* d_out, int out_size)
{
    const float* pair   = (const float*)d_in[0];
    const int*   mask   = (const int*)d_in[1];
    const float* ln_w   = (const float*)d_in[2];
    const float* ln_b   = (const float*)d_in[3];
    const float* w_bias = (const float*)d_in[4];
    const float* wq     = (const float*)d_in[5];
    const float* wk     = (const float*)d_in[6];
    const float* wv     = (const float*)d_in[7];
    const float* wg     = (const float*)d_in[8];
    const float* wo     = (const float*)d_in[9];
    float* out = (float*)d_out;

    (void)in_sizes; (void)n_in; (void)out_size;

    cudaFuncSetAttribute(proj_fused,
                         cudaFuncAttributeMaxDynamicSharedMemorySize, PROJ_SMEM_BYTES);
    proj_fused<<<dim3(148, 2), 256, PROJ_SMEM_BYTES>>>(
        pair, ln_w, ln_b, w_bias, wq, wk, wv, wg);

    cudaFuncSetAttribute(attn_fp16,
                         cudaFuncAttributeMaxDynamicSharedMemorySize, ATTN_SMEM_BYTES);
    attn_fp16<<<dim3(NN, HH), 256, ATTN_SMEM_BYTES>>>(mask);

    cudaFuncSetAttribute(out_fp16,
                         cudaFuncAttributeMaxDynamicSharedMemorySize, OUT_SMEM_BYTES);
    out_fp16<<<592, 256, OUT_SMEM_BYTES>>>(wo, out);
}

// round 16
// speedup vs baseline: 1.0232x; 1.0232x over previous
#include <cuda_runtime.h>
#include <cuda_fp16.h>
#include <math.h>
#include <stdint.h>

#define NN 384
#define CC 128
#define HH 4
#define MM (NN*NN)

// Scratch (allocation-free: __device__ globals)
__device__ __half d_x[(size_t)MM*CC];      // layernormed pair (fp16; LN math fp32)
__device__ __half d_y[(size_t)MM*512];     // [q|k|v|g] as fp16, q pre-scaled
__device__ __half d_bias[(size_t)HH*MM];   // bias[h, q, k] (fp16; computed fp32)
__device__ __half d_o[(size_t)MM*CC];      // attention output (fp16)

// ---- fp16 tensor-core helpers (m16n8k16, fp32 accum) ----
__device__ __forceinline__ void mma_f16(float& c0, float& c1, float& c2, float& c3,
                                        unsigned a0, unsigned a1, unsigned a2, unsigned a3,
                                        unsigned b0, unsigned b1) {
    asm("mma.sync.aligned.m16n8k16.row.col.f32.f16.f16.f32 "
        "{%0,%1,%2,%3}, {%4,%5,%6,%7}, {%8,%9}, {%0,%1,%2,%3};"
        : "+f"(c0), "+f"(c1), "+f"(c2), "+f"(c3)
        : "r"(a0), "r"(a1), "r"(a2), "r"(a3), "r"(b0), "r"(b1));
}
__device__ __forceinline__ unsigned h2u(float lo, float hi) {
    __half2 h = __floats2half2_rn(lo, hi);
    return reinterpret_cast<unsigned&>(h);
}

// ---------------------------------------------------------------------------
// Kernel 1: LayerNorm + pair bias. LN math fp32; x stored fp16; bias fp16.
// ---------------------------------------------------------------------------
__global__ __launch_bounds__(256) void ln_bias_kernel(
    const float* __restrict__ pair,
    const float* __restrict__ ln_w,
    const float* __restrict__ ln_b,
    const float* __restrict__ w_bias)
{
    int warp = threadIdx.x >> 5, lane = threadIdx.x & 31;
    int r = blockIdx.x * 8 + warp;
    if (r >= MM) return;

    float4 v = ((const float4*)(pair + (size_t)r * CC))[lane];
    float s  = v.x + v.y + v.z + v.w;
    float sq = v.x*v.x + v.y*v.y + v.z*v.z + v.w*v.w;
    #pragma unroll
    for (int o = 16; o; o >>= 1) {
        s  += __shfl_xor_sync(0xffffffffu, s,  o);
        sq += __shfl_xor_sync(0xffffffffu, sq, o);
    }
    float mean = s * (1.0f / CC);
    float var  = sq * (1.0f / CC) - mean * mean;
    float inv  = rsqrtf(var + 1e-5f);

    float4 w = ((const float4*)ln_w)[lane];
    float4 b = ((const float4*)ln_b)[lane];
    float4 xn;
    xn.x = (v.x - mean) * inv * w.x + b.x;
    xn.y = (v.y - mean) * inv * w.y + b.y;
    xn.z = (v.z - mean) * inv * w.z + b.z;
    xn.w = (v.w - mean) * inv * w.w + b.w;
    uint2 xo;
    xo.x = h2u(xn.x, xn.y);
    xo.y = h2u(xn.z, xn.w);
    *(uint2*)&d_x[(size_t)r * CC + lane * 4] = xo;

    float accb0 = 0.f, accb1 = 0.f, accb2 = 0.f, accb3 = 0.f;
    float xv[4] = {xn.x, xn.y, xn.z, xn.w};
    #pragma unroll
    for (int i = 0; i < 4; i++) {
        float4 wb = ((const float4*)w_bias)[lane * 4 + i];
        accb0 += xv[i] * wb.x;
        accb1 += xv[i] * wb.y;
        accb2 += xv[i] * wb.z;
        accb3 += xv[i] * wb.w;
    }
    #pragma unroll
    for (int o = 16; o; o >>= 1) {
        accb0 += __shfl_xor_sync(0xffffffffu, accb0, o);
        accb1 += __shfl_xor_sync(0xffffffffu, accb1, o);
        accb2 += __shfl_xor_sync(0xffffffffu, accb2, o);
        accb3 += __shfl_xor_sync(0xffffffffu, accb3, o);
    }
    if (lane == 0) {
        d_bias[(size_t)0 * MM + r] = __float2half(accb0);
        d_bias[(size_t)1 * MM + r] = __float2half(accb1);
        d_bias[(size_t)2 * MM + r] = __float2half(accb2);
        d_bias[(size_t)3 * MM + r] = __float2half(accb3);
    }
}

// ---------------------------------------------------------------------------
// Kernel 2: projections, persistent-W fp16 m16n8k16 GEMM. X fp16.
// Grid (148,2). W resident (Wt[n][k], stride 136). Double-buffered X.
// ---------------------------------------------------------------------------
#define PJW 136
#define PROJ_SMEM_BYTES ((256*PJW + 2*64*PJW) * 2)   // 104448

__global__ __launch_bounds__(256) void proj_fp16(
    const float* __restrict__ wq, const float* __restrict__ wk,
    const float* __restrict__ wv, const float* __restrict__ wg)
{
    extern __shared__ char psm[];
    __half* Wt = (__half*)psm;                 // [256][136]
    __half* Xb = Wt + 256 * PJW;               // [2][64][136]

    int tid = threadIdx.x, lane = tid & 31, warp = tid >> 5;
    int g = lane >> 2, t = lane & 3;
    int slot = blockIdx.x;
    int ph = blockIdx.y;                       // 0: wq|wk, 1: wv|wg
    int mhalf = warp >> 2;
    int cq = warp & 3;

    const float* w0 = (ph == 0) ? wq : wv;
    const float* w1 = (ph == 0) ? wk : wg;
    for (int i = tid; i < 256 * 128; i += 256) {
        int n = i & 255, k = i >> 8;
        const float* w = (n < 128) ? w0 : w1;
        Wt[n * PJW + k] = __float2half(w[(size_t)k * 128 + (n & 127)]);
    }

    {
        int m0 = slot * 64;
        int rsub = tid >> 5, col = (tid & 31) * 4;
        #pragma unroll
        for (int j = 0; j < 8; j++) {
            int row = j * 8 + rsub;
            uint2 v = *(const uint2*)&d_x[(size_t)(m0 + row) * 128 + col];
            *(uint2*)&Xb[row * PJW + col] = v;
        }
    }
    __syncthreads();

    float scale = (ph == 0 && cq < 2) ? 0.17677669529663687f : 1.0f;
    int colbase = cq * 64;
    int buf = 0;

    for (int mtile = slot; mtile < 2304; mtile += 148) {
        int mnext = mtile + 148;
        bool has_next = (mnext < 2304);

        uint2 pf[8];
        if (has_next) {
            int rsub = tid >> 5, col = (tid & 31) * 4;
            const __half* src = d_x + (size_t)(mnext * 64) * 128;
            #pragma unroll
            for (int j = 0; j < 8; j++)
                pf[j] = *(const uint2*)&src[(size_t)(j * 8 + rsub) * 128 + col];
        }

        const __half* Xs = Xb + buf * (64 * PJW);
        float c[16][4];
        #pragma unroll
        for (int i = 0; i < 16; i++)
            #pragma unroll
            for (int j = 0; j < 4; j++) c[i][j] = 0.f;

        int r0 = mhalf * 32;
        #pragma unroll
        for (int k16 = 0; k16 < 8; k16++) {
            int k0 = k16 * 16;
            unsigned a0 = *(const unsigned*)&Xs[(r0 + g) * PJW + k0 + 2*t];
            unsigned a1 = *(const unsigned*)&Xs[(r0 + 8 + g) * PJW + k0 + 2*t];
            unsigned a2 = *(const unsigned*)&Xs[(r0 + g) * PJW + k0 + 2*t + 8];
            unsigned a3 = *(const unsigned*)&Xs[(r0 + 8 + g) * PJW + k0 + 2*t + 8];
            unsigned a4 = *(const unsigned*)&Xs[(r0 + 16 + g) * PJW + k0 + 2*t];
            unsigned a5 = *(const unsigned*)&Xs[(r0 + 24 + g) * PJW + k0 + 2*t];
            unsigned a6 = *(const unsigned*)&Xs[(r0 + 16 + g) * PJW + k0 + 2*t + 8];
            unsigned a7 = *(const unsigned*)&Xs[(r0 + 24 + g) * PJW + k0 + 2*t + 8];
            #pragma unroll
            for (int nb = 0; nb < 8; nb++) {
                int n = colbase + nb * 8 + g;
                unsigned b0 = *(const unsigned*)&Wt[n * PJW + k0 + 2*t];
                unsigned b1 = *(const unsigned*)&Wt[n * PJW + k0 + 2*t + 8];
                mma_f16(c[nb][0], c[nb][1], c[nb][2], c[nb][3],
                        a0, a1, a2, a3, b0, b1);
                mma_f16(c[8+nb][0], c[8+nb][1], c[8+nb][2], c[8+nb][3],
                        a4, a5, a6, a7, b0, b1);
            }
        }

        {
            int r = mtile * 64 + mhalf * 32;
            #pragma unroll
            for (int nb = 0; nb < 8; nb++) {
                int col = ph * 256 + colbase + nb * 8 + 2 * t;
                *(unsigned*)&d_y[(size_t)(r + g) * 512 + col] =
                    h2u(c[nb][0] * scale, c[nb][1] * scale);
                *(unsigned*)&d_y[(size_t)(r + 8 + g) * 512 + col] =
                    h2u(c[nb][2] * scale, c[nb][3] * scale);
                *(unsigned*)&d_y[(size_t)(r + 16 + g) * 512 + col] =
                    h2u(c[8+nb][0] * scale, c[8+nb][1] * scale);
                *(unsigned*)&d_y[(size_t)(r + 24 + g) * 512 + col] =
                    h2u(c[8+nb][2] * scale, c[8+nb][3] * scale);
            }
        }

        __syncthreads();
        if (has_next) {
            __half* dst = Xb + (buf ^ 1) * (64 * PJW);
            int rsub = tid >> 5, col = (tid & 31) * 4;
            #pragma unroll
            for (int j = 0; j < 8; j++)
                *(uint2*)&dst[(j * 8 + rsub) * PJW + col] = pf[j];
        }
        __syncthreads();
        buf ^= 1;
    }
}

// ---------------------------------------------------------------------------
// Kernel 3: attention per (b,h), fp16 m16n8k16 flash. Bias fp16. d_o fp16.
// ---------------------------------------------------------------------------
#define AKS 40
#define AVS 392
#define ATTN_SMEM_BYTES (384*AKS*2 + 32*AVS*2 + 384*4)

__global__ __launch_bounds__(256) void attn_fp16(const int* __restrict__ mask)
{
    extern __shared__ char asm_[];
    __half* Ks = (__half*)asm_;                     // [384][40]
    __half* Vt = Ks + 384 * AKS;                    // [32][392]
    float*  Am = (float*)(Vt + 32 * AVS);           // [384]

    int b = blockIdx.x, h = blockIdx.y;
    int tid = threadIdx.x, lane = tid & 31, w = tid >> 5;
    int g = lane >> 2, t = lane & 3;
    const __half* Yb = d_y + (size_t)b * (NN * 512);

    for (int idx = tid; idx < 384 * 8; idx += 256) {
        int key = idx >> 3, d4 = (idx & 7) * 4;
        uint2 v = *(const uint2*)&Yb[(size_t)key * 512 + 128 + h * 32 + d4];
        *(uint2*)&Ks[key * AKS + d4] = v;
    }
    for (int idx = tid; idx < 384 * 32; idx += 256) {
        int key = idx >> 5, d = idx & 31;
        Vt[d * AVS + key] = Yb[(size_t)key * 512 + 256 + h * 32 + d];
    }
    for (int k = tid; k < NN; k += 256)
        Am[k] = (mask[(size_t)b * NN + k] != 0) ? 0.f : -1e9f;
    __syncthreads();

    for (int mt = w; mt < 24; mt += 8) {
        int q0 = mt * 16;

        unsigned aq[2][4];
        #pragma unroll
        for (int s = 0; s < 2; s++) {
            int dc = h * 32 + 16 * s + 2 * t;
            aq[s][0] = *(const unsigned*)&Yb[(size_t)(q0 + g) * 512 + dc];
            aq[s][1] = *(const unsigned*)&Yb[(size_t)(q0 + 8 + g) * 512 + dc];
            aq[s][2] = *(const unsigned*)&Yb[(size_t)(q0 + g) * 512 + dc + 8];
            aq[s][3] = *(const unsigned*)&Yb[(size_t)(q0 + 8 + g) * 512 + dc + 8];
        }

        float oc[4][4];
        #pragma unroll
        for (int dn = 0; dn < 4; dn++)
            #pragma unroll
            for (int j = 0; j < 4; j++) oc[dn][j] = 0.f;
        float sum_lo = 0.f, sum_hi = 0.f;

        const __half* br_lo = d_bias + (size_t)h * MM + (size_t)(q0 + g) * NN;
        const __half* br_hi = br_lo + (size_t)8 * NN;

        for (int kb = 0; kb < 6; kb++) {
            float pc[8][4];

            #pragma unroll
            for (int nb = 0; nb < 8; nb++) {
                int k8 = kb * 64 + nb * 8;
                float c0 = 0.f, c1 = 0.f, c2 = 0.f, c3 = 0.f;
                #pragma unroll
                for (int s = 0; s < 2; s++) {
                    unsigned b0 = *(const unsigned*)&Ks[(k8 + g) * AKS + 16*s + 2*t];
                    unsigned b1 = *(const unsigned*)&Ks[(k8 + g) * AKS + 16*s + 2*t + 8];
                    mma_f16(c0, c1, c2, c3,
                            aq[s][0], aq[s][1], aq[s][2], aq[s][3], b0, b1);
                }
                int col = k8 + 2 * t;
                float2 blo = __half22float2(*(const __half2*)&br_lo[col]);
                float2 bhi = __half22float2(*(const __half2*)&br_hi[col]);
                float2 am  = *(const float2*)&Am[col];
                float e0 = __expf(c0 + blo.x + am.x);
                float e1 = __expf(c1 + blo.y + am.y);
                float e2 = __expf(c2 + bhi.x + am.x);
                float e3 = __expf(c3 + bhi.y + am.y);
                sum_lo += e0 + e1;
                sum_hi += e2 + e3;
                pc[nb][0] = e0; pc[nb][1] = e1; pc[nb][2] = e2; pc[nb][3] = e3;
            }

            #pragma unroll
            for (int j = 0; j < 4; j++) {
                unsigned a0 = h2u(pc[2*j][0],   pc[2*j][1]);
                unsigned a1 = h2u(pc[2*j][2],   pc[2*j][3]);
                unsigned a2 = h2u(pc[2*j+1][0], pc[2*j+1][1]);
                unsigned a3 = h2u(pc[2*j+1][2], pc[2*j+1][3]);
                int kg = kb * 64 + j * 16;
                #pragma unroll
                for (int dn = 0; dn < 4; dn++) {
                    unsigned b0 = *(const unsigned*)&Vt[(dn*8 + g) * AVS + kg + 2*t];
                    unsigned b1 = *(const unsigned*)&Vt[(dn*8 + g) * AVS + kg + 2*t + 8];
                    mma_f16(oc[dn][0], oc[dn][1], oc[dn][2], oc[dn][3],
                            a0, a1, a2, a3, b0, b1);
                }
            }
        }

        #pragma unroll
        for (int o = 1; o <= 2; o <<= 1) {
            sum_lo += __shfl_xor_sync(0xffffffffu, sum_lo, o);
            sum_hi += __shfl_xor_sync(0xffffffffu, sum_hi, o);
        }
        float inv_lo = 1.f / sum_lo;
        float inv_hi = 1.f / sum_hi;

        __half* ob = d_o + ((size_t)b * NN + q0) * CC + h * 32;
        #pragma unroll
        for (int dn = 0; dn < 4; dn++) {
            *(unsigned*)&ob[(size_t)g * CC + dn * 8 + 2 * t] =
                h2u(oc[dn][0] * inv_lo, oc[dn][1] * inv_lo);
            *(unsigned*)&ob[(size_t)(g + 8) * CC + dn * 8 + 2 * t] =
                h2u(oc[dn][2] * inv_hi, oc[dn][3] * inv_hi);
        }
    }
}

// ---------------------------------------------------------------------------
// Kernel 4: out = (o * sigmoid(g)) @ wo, persistent-W fp16 m16n8k16.
// ---------------------------------------------------------------------------
#define OGW 136
#define OUT_SMEM_BYTES ((128*OGW + 64*OGW) * 2)

__global__ __launch_bounds__(256) void out_fp16(
    const float* __restrict__ wo, float* __restrict__ out)
{
    extern __shared__ char osm[];
    __half* Wh = (__half*)osm;            // [128][136]
    __half* Ah = Wh + 128 * OGW;          // [64][136]

    int tid = threadIdx.x, lane = tid & 31, warp = tid >> 5;
    int g = lane >> 2, t = lane & 3;
    int mhalf = warp >> 2;
    int cq = warp & 3;

    for (int i = tid; i < 128 * 128; i += 256) {
        int n = i & 127, k = i >> 7;
        Wh[n * OGW + k] = __float2half(wo[(size_t)k * 128 + n]);
    }

    for (int tile = blockIdx.x; tile < 2304; tile += 592) {
        int m0 = tile * 64;
        __syncthreads();
        for (int i = tid; i < 64 * 32; i += 256) {
            int row = i >> 5, c4 = (i & 31) * 4;
            uint2 ou = *(const uint2*)&d_o[(size_t)(m0 + row) * 128 + c4];
            uint2 gu = *(const uint2*)&d_y[(size_t)(m0 + row) * 512 + 384 + c4];
            float2 of01 = __half22float2(reinterpret_cast<__half2&>(ou.x));
            float2 of23 = __half22float2(reinterpret_cast<__half2&>(ou.y));
            float2 gf01 = __half22float2(reinterpret_cast<__half2&>(gu.x));
            float2 gf23 = __half22float2(reinterpret_cast<__half2&>(gu.y));
            float a0 = of01.x * (1.f / (1.f + __expf(-gf01.x)));
            float a1 = of01.y * (1.f / (1.f + __expf(-gf01.y)));
            float a2 = of23.x * (1.f / (1.f + __expf(-gf23.x)));
            float a3 = of23.y * (1.f / (1.f + __expf(-gf23.y)));
            uint2 o;
            o.x = h2u(a0, a1);
            o.y = h2u(a2, a3);
            *(uint2*)&Ah[row * OGW + c4] = o;
        }
        __syncthreads();

        float c[2][4][4];
        #pragma unroll
        for (int mm = 0; mm < 2; mm++)
            #pragma unroll
            for (int nb = 0; nb < 4; nb++)
                #pragma unroll
                for (int j = 0; j < 4; j++) c[mm][nb][j] = 0.f;

        #pragma unroll
        for (int k16 = 0; k16 < 8; k16++) {
            int k0 = k16 * 16;
            #pragma unroll
            for (int mm = 0; mm < 2; mm++) {
                int r0 = mhalf * 32 + mm * 16;
                unsigned a0 = *(const unsigned*)&Ah[(r0 + g) * OGW + k0 + 2*t];
                unsigned a1 = *(const unsigned*)&Ah[(r0 + 8 + g) * OGW + k0 + 2*t];
                unsigned a2 = *(const unsigned*)&Ah[(r0 + g) * OGW + k0 + 2*t + 8];
                unsigned a3 = *(const unsigned*)&Ah[(r0 + 8 + g) * OGW + k0 + 2*t + 8];
                #pragma unroll
                for (int nb = 0; nb < 4; nb++) {
                    int n = cq * 32 + nb * 8 + g;
                    unsigned b0 = *(const unsigned*)&Wh[n * OGW + k0 + 2*t];
                    unsigned b1 = *(const unsigned*)&Wh[n * OGW + k0 + 2*t + 8];
                    mma_f16(c[mm][nb][0], c[mm][nb][1], c[mm][nb][2], c[mm][nb][3],
                            a0, a1, a2, a3, b0, b1);
                }
            }
        }

        #pragma unroll
        for (int mm = 0; mm < 2; mm++) {
            int r = m0 + mhalf * 32 + mm * 16;
            #pragma unroll
            for (int nb = 0; nb < 4; nb++) {
                int col = cq * 32 + nb * 8 + 2 * t;
                *(float2*)&out[(size_t)(r + g) * 128 + col] =
                    make_float2(c[mm][nb][0], c[mm][nb][1]);
                *(float2*)&out[(size_t)(r + 8 + g) * 128 + col] =
                    make_float2(c[mm][nb][2], c[mm][nb][3]);
            }
        }
    }
}

// ---------------------------------------------------------------------------
extern "C" void kernel_launch(void* const* d_in, const int* in_sizes, int n_in,
                              void* d_out, int out_size)
{
    const float* pair   = (const float*)d_in[0];
    const int*   mask   = (const int*)d_in[1];
    const float* ln_w   = (const float*)d_in[2];
    const float* ln_b   = (const float*)d_in[3];
    const float* w_bias = (const float*)d_in[4];
    const float* wq     = (const float*)d_in[5];
    const float* wk     = (const float*)d_in[6];
    const float* wv     = (const float*)d_in[7];
    const float* wg     = (const float*)d_in[8];
    const float* wo     = (const float*)d_in[9];
    float* out = (float*)d_out;

    (void)in_sizes; (void)n_in; (void)out_size;

    ln_bias_kernel<<<MM / 8, 256>>>(pair, ln_w, ln_b, w_bias);

    cudaFuncSetAttribute(proj_fp16,
                         cudaFuncAttributeMaxDynamicSharedMemorySize, PROJ_SMEM_BYTES);
    proj_fp16<<<dim3(148, 2), 256, PROJ_SMEM_BYTES>>>(wq, wk, wv, wg);

    cudaFuncSetAttribute(attn_fp16,
                         cudaFuncAttributeMaxDynamicSharedMemorySize, ATTN_SMEM_BYTES);
    attn_fp16<<<dim3(NN, HH), 256, ATTN_SMEM_BYTES>>>(mask);

    cudaFuncSetAttribute(out_fp16,
                         cudaFuncAttributeMaxDynamicSharedMemorySize, OUT_SMEM_BYTES);
    out_fp16<<<592, 256, OUT_SMEM_BYTES>>>(wo, out);
}